// round 10
// baseline (speedup 1.0000x reference)
#include <cuda_runtime.h>
#include <cuda_bf16.h>
#include <math.h>
#include <stdint.h>

#define T_STEPS 1024
#define BATCH   32
#define INP     512
#define HID     512
#define G4      2048   // 4*HID
#define MTOT    (T_STEPS * BATCH)   // 32768

// ---------------- scratch ----------------
__device__ float g_xw[(size_t)T_STEPS * G4 * BATCH]; // [t][col][b]  (256 MB)
__device__ __nv_bfloat16 g_xhi[(size_t)MTOT * INP];  // x hi  [m][k]
__device__ __nv_bfloat16 g_xlo[(size_t)MTOT * INP];  // x lo
__device__ __nv_bfloat16 g_whi[(size_t)G4 * INP];    // W^T hi [n][k]
__device__ __nv_bfloat16 g_wlo[(size_t)G4 * INP];    // W^T lo
__device__ signed char g_hq[2][32 * 1024];           // h 2-limb int8 ping-pong:
                                                     // [ping][b*1024 + c*128 + limb*64 + ko]
__device__ unsigned int g_bar2[2];                   // per-batch-half barrier counters
__device__ unsigned int g_umax_bits;                 // max|U| as uint bits

// ================= helpers =================
__device__ __forceinline__ uint32_t smem_to_u32(const void* p) {
    uint32_t a;
    asm("{ .reg .u64 t; cvta.to.shared.u64 t, %1; cvt.u32.u64 %0, t; }"
        : "=r"(a) : "l"(p));
    return a;
}
#define SMEM_SWIZZLE_128B(off) ((off) ^ (((off) >> 3) & 0x70))

__device__ __forceinline__ void cp_async16(uint32_t smem_addr, const void* gptr) {
    asm volatile("cp.async.cg.shared.global [%0], [%1], 16;"
                 :: "r"(smem_addr), "l"(gptr) : "memory");
}
__device__ __forceinline__ void cp_async_commit() {
    asm volatile("cp.async.commit_group;" ::: "memory");
}
template <int N>
__device__ __forceinline__ void cp_async_wait() {
    asm volatile("cp.async.wait_group %0;" :: "n"(N) : "memory");
}

__device__ __forceinline__ void ldmatrix_x4(uint32_t* r, uint32_t addr) {
    asm volatile("ldmatrix.sync.aligned.m8n8.x4.shared.b16 {%0,%1,%2,%3}, [%4];"
                 : "=r"(r[0]), "=r"(r[1]), "=r"(r[2]), "=r"(r[3]) : "r"(addr));
}
__device__ __forceinline__ void mma_bf16(float* c, const uint32_t* a, const uint32_t* b) {
    asm volatile(
        "mma.sync.aligned.m16n8k16.row.col.f32.bf16.bf16.f32 "
        "{%0,%1,%2,%3}, {%4,%5,%6,%7}, {%8,%9}, {%0,%1,%2,%3};"
        : "+f"(c[0]), "+f"(c[1]), "+f"(c[2]), "+f"(c[3])
        : "r"(a[0]), "r"(a[1]), "r"(a[2]), "r"(a[3]), "r"(b[0]), "r"(b[1]));
}
__device__ __forceinline__ void mma_s8(int* c, const uint32_t* a, const uint32_t* b) {
    asm volatile(
        "mma.sync.aligned.m16n8k32.row.col.s32.s8.s8.s32 "
        "{%0,%1,%2,%3}, {%4,%5,%6,%7}, {%8,%9}, {%0,%1,%2,%3};"
        : "+r"(c[0]), "+r"(c[1]), "+r"(c[2]), "+r"(c[3])
        : "r"(a[0]), "r"(a[1]), "r"(a[2]), "r"(a[3]), "r"(b[0]), "r"(b[1]));
}
__device__ __forceinline__ float sigmoidf_(float v) {
    return 1.f / (1.f + __expf(-v));
}
__device__ __forceinline__ float tanhf_fast(float v) {
    // tanh(x) = 1 - 2/(1+exp(2x)); rel err ~1e-7, saturates correctly
    return 1.f - 2.f / (1.f + __expf(2.f * v));
}

// ---------------- init ----------------
__global__ void lstm_init_kernel() {
    int idx = blockIdx.x * blockDim.x + threadIdx.x;
    int n = 2 * 32 * 1024 / 4;
    for (int i = idx; i < n; i += gridDim.x * blockDim.x)
        ((int*)g_hq)[i] = 0;
    if (idx < 2) g_bar2[idx] = 0u;
    if (idx == 0) g_umax_bits = 0u;
}

// ---------------- max|U| reduction ----------------
__global__ __launch_bounds__(256) void umax_kernel(const float* __restrict__ U) {
    __shared__ float red[256];
    float m = 0.f;
    int n = G4 * INP;
    for (int i = blockIdx.x * 256 + threadIdx.x; i < n; i += gridDim.x * 256)
        m = fmaxf(m, fabsf(U[i]));
    red[threadIdx.x] = m;
    __syncthreads();
    for (int s = 128; s > 0; s >>= 1) {
        if (threadIdx.x < s) red[threadIdx.x] = fmaxf(red[threadIdx.x], red[threadIdx.x + s]);
        __syncthreads();
    }
    if (threadIdx.x == 0)
        atomicMax(&g_umax_bits, __float_as_uint(red[0]));
}

// ---------------- convert x -> bf16 hi/lo ----------------
__global__ __launch_bounds__(256) void xcvt_kernel(const float* __restrict__ x) {
    size_t i = ((size_t)blockIdx.x * 256 + threadIdx.x) * 4;
    float4 v = *(const float4*)(x + i);
    __nv_bfloat16 h0 = __float2bfloat16(v.x), h1 = __float2bfloat16(v.y),
                  h2 = __float2bfloat16(v.z), h3 = __float2bfloat16(v.w);
    __nv_bfloat16 l0 = __float2bfloat16(v.x - __bfloat162float(h0));
    __nv_bfloat16 l1 = __float2bfloat16(v.y - __bfloat162float(h1));
    __nv_bfloat16 l2 = __float2bfloat16(v.z - __bfloat162float(h2));
    __nv_bfloat16 l3 = __float2bfloat16(v.w - __bfloat162float(h3));
    __nv_bfloat162* ph = (__nv_bfloat162*)(g_xhi + i);
    __nv_bfloat162* pl = (__nv_bfloat162*)(g_xlo + i);
    ph[0] = __nv_bfloat162(h0, h1); ph[1] = __nv_bfloat162(h2, h3);
    pl[0] = __nv_bfloat162(l0, l1); pl[1] = __nv_bfloat162(l2, l3);
}

// ---------------- convert + transpose W -> [n][k] bf16 hi/lo ----------------
__global__ __launch_bounds__(256) void wcvt_kernel(const float* __restrict__ W) {
    __shared__ float tile[32][33];
    int n0 = blockIdx.x * 32, k0 = blockIdx.y * 32;
    int tx = threadIdx.x & 31, ty = threadIdx.x >> 5;   // 32 x 8
    #pragma unroll
    for (int r = 0; r < 4; r++)
        tile[ty + 8 * r][tx] = W[(size_t)(k0 + ty + 8 * r) * G4 + n0 + tx];
    __syncthreads();
    #pragma unroll
    for (int r = 0; r < 4; r++) {
        float v = tile[tx][ty + 8 * r];
        __nv_bfloat16 hi = __float2bfloat16(v);
        __nv_bfloat16 lo = __float2bfloat16(v - __bfloat162float(hi));
        size_t o = (size_t)(n0 + ty + 8 * r) * INP + k0 + tx;
        g_whi[o] = hi;
        g_wlo[o] = lo;
    }
}

// ---------------- phase 1: mma.sync bf16 hi/lo GEMM (unchanged) ----------------
#define GEMM_SMEM_BYTES (1024 + 2 * 65536)

__global__ __launch_bounds__(256, 1) void xw_tc_kernel(const float* __restrict__ bias)
{
    extern __shared__ char smem[];
    const uint32_t sb = smem_to_u32(smem);
    const int tid  = threadIdx.x;
    const int wid  = tid >> 5;
    const int lane = tid & 31;
    const int n0 = blockIdx.x * 128;
    const int m0 = blockIdx.y * 128;
    float* bias_sm = (float*)smem;

    if (tid < 128) bias_sm[tid] = bias[n0 + tid];

    const int wm = (wid & 1) * 64;
    const int wn = (wid >> 1) * 32;

    const uint32_t aRow = (uint32_t)(lane & 15);
    const uint32_t aCol = (uint32_t)(((lane >> 4) & 1) * 16);
    const uint32_t bRow = (uint32_t)(((lane >> 4) & 1) * 8 + (lane & 7));
    const uint32_t bCol = (uint32_t)(((lane >> 3) & 1) * 16);

    uint32_t aOff[4], bOff[2];
    #pragma unroll
    for (int im = 0; im < 4; im++)
        aOff[im] = (uint32_t)(wm + 16 * im + aRow) * 128 + aCol;
    #pragma unroll
    for (int in_ = 0; in_ < 2; in_++)
        bOff[in_] = (uint32_t)(wn + 16 * in_ + bRow) * 128 + bCol;

    float c[4][4][4];
    #pragma unroll
    for (int i = 0; i < 4; i++)
        #pragma unroll
        for (int j = 0; j < 4; j++)
            #pragma unroll
            for (int k = 0; k < 4; k++) c[i][j][k] = 0.f;

    const int lrow0 = tid >> 3;
    const int lc16  = tid & 7;

    auto issue_chunk = [&](int ch, int buf) {
        const uint32_t bbase = 1024u + (uint32_t)buf * 65536u;
        const int kb = ch * 64;
        #pragma unroll
        for (int it = 0; it < 4; it++) {
            int row = lrow0 + it * 32;
            uint32_t sw = SMEM_SWIZZLE_128B((uint32_t)(row * 128 + lc16 * 16));
            const __nv_bfloat16* gA = g_xhi + (size_t)(m0 + row) * INP + kb + lc16 * 8;
            const __nv_bfloat16* gAl= g_xlo + (size_t)(m0 + row) * INP + kb + lc16 * 8;
            const __nv_bfloat16* gB = g_whi + (size_t)(n0 + row) * INP + kb + lc16 * 8;
            const __nv_bfloat16* gBl= g_wlo + (size_t)(n0 + row) * INP + kb + lc16 * 8;
            cp_async16(sb + bbase +         sw, gA);
            cp_async16(sb + bbase + 16384 + sw, gAl);
            cp_async16(sb + bbase + 32768 + sw, gB);
            cp_async16(sb + bbase + 49152 + sw, gBl);
        }
        cp_async_commit();
    };

    issue_chunk(0, 0);

    for (int ch = 0; ch < 8; ch++) {
        const int buf = ch & 1;
        if (ch < 7) issue_chunk(ch + 1, buf ^ 1);
        if (ch < 7) cp_async_wait<1>(); else cp_async_wait<0>();
        __syncthreads();

        const uint32_t bbase = sb + 1024u + (uint32_t)buf * 65536u;
        #pragma unroll
        for (int ks = 0; ks < 4; ks++) {
            uint32_t ahi[4][4], alo[4][4], bhi[4][4], blo[4][4];
            #pragma unroll
            for (int im = 0; im < 4; im++) {
                uint32_t sw = SMEM_SWIZZLE_128B(aOff[im] + ks * 32);
                ldmatrix_x4(ahi[im], bbase + sw);
                ldmatrix_x4(alo[im], bbase + 16384 + sw);
            }
            #pragma unroll
            for (int ib = 0; ib < 2; ib++) {
                uint32_t sw = SMEM_SWIZZLE_128B(bOff[ib] + ks * 32);
                ldmatrix_x4(bhi[ib], bbase + 32768 + sw);
                ldmatrix_x4(blo[ib], bbase + 49152 + sw);
            }
            #pragma unroll
            for (int im = 0; im < 4; im++) {
                #pragma unroll
                for (int jn = 0; jn < 4; jn++) {
                    uint32_t* bh = &bhi[jn >> 1][(jn & 1) * 2];
                    uint32_t* bl = &blo[jn >> 1][(jn & 1) * 2];
                    mma_bf16(c[im][jn], ahi[im], bh);
                    mma_bf16(c[im][jn], ahi[im], bl);
                    mma_bf16(c[im][jn], alo[im], bh);
                }
            }
        }
        __syncthreads();
    }

    float* cs = (float*)(smem + 1024);   // [128][129]
    const int crow = lane >> 2;
    const int ccol = (lane & 3) * 2;
    #pragma unroll
    for (int im = 0; im < 4; im++) {
        #pragma unroll
        for (int jn = 0; jn < 4; jn++) {
            int r0 = wm + 16 * im + crow;
            int cc = wn + 8 * jn + ccol;
            cs[r0 * 129 + cc]           = c[im][jn][0];
            cs[r0 * 129 + cc + 1]       = c[im][jn][1];
            cs[(r0 + 8) * 129 + cc]     = c[im][jn][2];
            cs[(r0 + 8) * 129 + cc + 1] = c[im][jn][3];
        }
    }
    __syncthreads();

    const int t0 = blockIdx.y * 4;
    for (int i = 0; i < 64; i++) {
        int ro = wid * 64 + i;
        int tl = ro >> 7, n = ro & 127;
        float v = cs[(tl * 32 + lane) * 129 + n] + bias_sm[n];
        g_xw[((size_t)(t0 + tl) * G4 + n0 + n) * BATCH + lane] = v;
    }
}

// ---------------- phase 2: int8 recurrence, batch-split + split barriers -------
// 128 CTAs x 256 threads. CTA = (unit-group ug = bid>>1, batch-half bh = bid&1):
// owns 8 hidden units (32 gate cols, gate-major n = g*8+u) x 16 batches.
// The h dependency graph is CLOSED under batch half: half-h CTAs produce and
// consume only batches [16h,16h+16). So each half runs its own 64-CTA barrier
// (g_bar2[h]) -- half the arrivals, half the poll contention, decoupled halves.
// Warp w owns K-chunk w (64 k, both limbs); issues AND consumes its own cp.asyncs.
// smem bytes:
//   [0     .. 16384)  h: 8 chunks of [16 b][128B = limb1|limb2], SW128
//   [16384 .. 49152)  U: 8 chunks of [32 n][128B]
//   [49152 .. 54272)  xw double buffer, 2 x [32 n][20 f] (stride 80B, 16 data)
//   [54272 .. 74752)  partials [8 w][16 m][40 f]
#define R_H   0
#define R_U   16384
#define R_XW  49152
#define R_P   54272
#define REC4_SMEM_BYTES 74752
#define NCTA  128

__global__ __launch_bounds__(256, 1) void lstm_rec_tc_kernel(
    const float* __restrict__ U, float* __restrict__ out, int write_tail)
{
    extern __shared__ char smem[];
    const uint32_t sb = smem_to_u32(smem);
    const int tid  = threadIdx.x;
    const int wid  = tid >> 5;
    const int lane = tid & 31;
    const int u0   = (blockIdx.x >> 1) * 8;      // unit group
    const int half = blockIdx.x & 1;             // batch half
    const int b0   = half * 16;
    unsigned int* barp = &g_bar2[half];

    const float s_U = fmaxf(__uint_as_float(g_umax_bits), 1e-30f);
    const float uinv = 127.f / s_U;
    const float sc1 = s_U / 16129.f;
    const float sc2 = sc1 / 254.f;

    // ---- quantize U slice -> smem int8 2-limb, chunked+swizzled ----
    for (int i = tid; i < 32 * HID; i += 256) {
        int k = i >> 5, n = i & 31;
        int gcol = u0 + (n & 7) + 512 * (n >> 3);
        float v = U[(size_t)k * G4 + gcol];
        float aq = v * uinv;
        int p1 = __float2int_rn(aq);
        p1 = max(-127, min(127, p1));
        int p2 = __float2int_rn((aq - (float)p1) * 254.f);
        int c = k >> 6, ko = k & 63;
        uint32_t base = (uint32_t)(R_U + c * 4096);
        *(signed char*)(smem + base + SMEM_SWIZZLE_128B((uint32_t)(n * 128 + ko))) =
            (signed char)p1;
        *(signed char*)(smem + base + SMEM_SWIZZLE_128B((uint32_t)(n * 128 + 64 + ko))) =
            (signed char)p2;
    }

    // ldmatrix lane address parts
    const uint32_t aRow = (uint32_t)(lane & 15);
    const uint32_t aCol = (uint32_t)(((lane >> 4) & 1) * 16);
    const uint32_t bRow = (uint32_t)(((lane >> 4) & 1) * 8 + (lane & 7));
    const uint32_t bCol = (uint32_t)(((lane >> 3) & 1) * 16);
    const uint32_t aBase = aRow * 128 + aCol;    // one m-tile (16 batches)
    const uint32_t bBase = bRow * 128 + bCol;    // n-tiles 0-1; +2048 for 2-3

    // activation mapping: thread (tid<128) owns (b = b0 + (tid>>3), u = tid&7)
    const int rb = tid >> 3;
    const int ua = tid & 7;
    float c_state = 0.f;

    float* p_sm = (float*)(smem + R_P);

    // xw prefetch: threads 0..127, 1 cp.async16 each; ALL threads commit
    auto issue_xw = [&](int t, int valid) {
        if (valid && tid < 128) {
            int n = tid >> 2, seg = tid & 3;
            int gcol = u0 + (n & 7) + 512 * (n >> 3);
            cp_async16(sb + R_XW + (uint32_t)((t & 1) * 2560 + n * 80 + seg * 16),
                       g_xw + ((size_t)t * G4 + gcol) * BATCH + b0 + seg * 4);
        }
        cp_async_commit();
    };
    // h chunk load: warp w loads chunk w, 4 cp/lane (16 rows x 8 segs)
    auto issue_h_chunk = [&](int R, int cc) {
        const signed char* hq = g_hq[R];
        #pragma unroll
        for (int j = 0; j < 4; j++) {
            int idx = lane + 32 * j;
            int b = idx >> 3, seg = idx & 7;
            uint32_t sw = SMEM_SWIZZLE_128B((uint32_t)(b * 128 + seg * 16));
            cp_async16(sb + R_H + cc * 2048 + sw,
                       hq + (b0 + b) * 1024 + cc * 128 + seg * 16);
        }
        cp_async_commit();
    };

    __syncthreads();            // U slice ready
    issue_xw(0, 1);

    for (int t = 0; t < T_STEPS; t++) {
        const int R = t & 1;

        issue_h_chunk(R, wid);              // group: h(t) chunk w
        issue_xw(t + 1, t + 1 < T_STEPS);   // group: xw(t+1) (maybe empty)
        cp_async_wait<1>();                 // drain everything except xw(t+1)

        int C1[4][4], C2[4][4];
        #pragma unroll
        for (int nt = 0; nt < 4; nt++)
            #pragma unroll
            for (int q = 0; q < 4; q++) { C1[nt][q] = 0; C2[nt][q] = 0; }

        const uint32_t hbse = sb + R_H + wid * 2048;
        const uint32_t ubse = sb + R_U + wid * 4096;
        #pragma unroll
        for (int kt = 0; kt < 2; kt++) {
            uint32_t aq1[4], aq2[4], bp1a[4], bp2a[4], bp1b[4], bp2b[4];
            ldmatrix_x4(aq1, hbse + SMEM_SWIZZLE_128B(aBase + kt * 32));
            ldmatrix_x4(aq2, hbse + SMEM_SWIZZLE_128B(aBase + 64 + kt * 32));
            ldmatrix_x4(bp1a, ubse + SMEM_SWIZZLE_128B(bBase + kt * 32));
            ldmatrix_x4(bp2a, ubse + SMEM_SWIZZLE_128B(bBase + 64 + kt * 32));
            ldmatrix_x4(bp1b, ubse + 2048 + SMEM_SWIZZLE_128B(bBase + kt * 32));
            ldmatrix_x4(bp2b, ubse + 2048 + SMEM_SWIZZLE_128B(bBase + 64 + kt * 32));
            #pragma unroll
            for (int nt = 0; nt < 4; nt++) {
                uint32_t* b1 = (nt < 2) ? &bp1a[(nt & 1) * 2] : &bp1b[(nt & 1) * 2];
                uint32_t* b2 = (nt < 2) ? &bp2a[(nt & 1) * 2] : &bp2b[(nt & 1) * 2];
                mma_s8(C1[nt], aq1, b1);
                mma_s8(C2[nt], aq1, b2);
                mma_s8(C2[nt], aq2, b1);
            }
        }

        // combine limbs -> float partials [w][16 m][40]
        {
            const int m  = lane >> 2;
            const int nn = 2 * (lane & 3);
            #pragma unroll
            for (int nt = 0; nt < 4; nt++) {
                int col = nt * 8 + nn;
                float e0 = (float)C1[nt][0] * sc1 + (float)C2[nt][0] * sc2;
                float e1 = (float)C1[nt][1] * sc1 + (float)C2[nt][1] * sc2;
                float e2 = (float)C1[nt][2] * sc1 + (float)C2[nt][2] * sc2;
                float e3 = (float)C1[nt][3] * sc1 + (float)C2[nt][3] * sc2;
                *(float2*)&p_sm[(wid * 16 + m) * 40 + col]     = make_float2(e0, e1);
                *(float2*)&p_sm[(wid * 16 + m + 8) * 40 + col] = make_float2(e2, e3);
            }
        }
        __syncthreads();   // partials + xw(t) visible to all threads

        // reduce + activations (tid < 128): thread owns (rb, ua)
        if (tid < 128) {
            const float* xw_sm = (const float*)(smem + R_XW + (t & 1) * 2560);
            float s[4];
            #pragma unroll
            for (int g = 0; g < 4; g++) {
                int n = g * 8 + ua;
                float v = xw_sm[n * 20 + rb];
                #pragma unroll
                for (int w = 0; w < 8; w++)
                    v += p_sm[(w * 16 + rb) * 40 + n];
                s[g] = v;
            }
            float ig = sigmoidf_(s[0]);
            float fg = sigmoidf_(s[1]);
            float gg = tanhf_fast(s[2]);
            float og = sigmoidf_(s[3]);
            float cnew = fg * c_state + ig * gg;
            float hnew = og * tanhf_fast(cnew);
            c_state = cnew;

            const int b = b0 + rb;

            // quantize h -> 2 int8 limbs (critical-path store first)
            float aq = hnew * 127.f;
            int q1 = __float2int_rn(aq);
            q1 = max(-127, min(127, q1));
            int q2 = __float2int_rn((aq - (float)q1) * 254.f);
            int uu = u0 + ua;
            int cc2 = uu >> 6, ko = uu & 63;
            signed char* dst = g_hq[R ^ 1] + b * 1024 + cc2 * 128 + ko;
            dst[0]  = (signed char)q1;
            dst[64] = (signed char)q2;

            out[((size_t)t * BATCH + b) * HID + u0 + ua] = hnew;
            if (write_tail && t == T_STEPS - 1) {
                out[(size_t)T_STEPS * BATCH * HID + (size_t)b * HID + u0 + ua] = hnew;
                out[(size_t)T_STEPS * BATCH * HID + BATCH * HID
                    + (size_t)b * HID + u0 + ua] = cnew;
            }
        }
        __syncthreads();   // h stores complete before the release below

        // per-half grid barrier (64 arrivals each, tid0 poll)
        if (t + 1 < T_STEPS) {
            if (tid == 0) {
                unsigned int target = 64u * (unsigned int)(t + 1);
                asm volatile("red.release.gpu.add.u32 [%0], %1;"
                             :: "l"(barp), "r"(1u) : "memory");
                unsigned int v;
                do {
                    asm volatile("ld.acquire.gpu.u32 %0, [%1];"
                                 : "=r"(v) : "l"(barp) : "memory");
                } while (v < target);
            }
            __syncthreads();
        }
    }
}

// ---------------- launch ----------------
extern "C" void kernel_launch(void* const* d_in, const int* in_sizes, int n_in,
                              void* d_out, int out_size)
{
    const float* x    = (const float*)d_in[0]; // (T,B,I)
    const float* W    = (const float*)d_in[1]; // (I,4H)
    const float* U    = (const float*)d_in[2]; // (H,4H)
    const float* bias = (const float*)d_in[3]; // (4H,)
    float* out = (float*)d_out;

    const long long need_tail = (long long)T_STEPS * BATCH * HID + 2LL * BATCH * HID;
    int write_tail = ((long long)out_size >= need_tail) ? 1 : 0;

    static int configured = 0;
    if (!configured) {
        cudaFuncSetAttribute(xw_tc_kernel,
                             cudaFuncAttributeMaxDynamicSharedMemorySize,
                             GEMM_SMEM_BYTES);
        cudaFuncSetAttribute(lstm_rec_tc_kernel,
                             cudaFuncAttributeMaxDynamicSharedMemorySize,
                             REC4_SMEM_BYTES);
        configured = 1;
    }

    lstm_init_kernel<<<64, 256>>>();
    umax_kernel<<<256, 256>>>(U);
    xcvt_kernel<<<(MTOT * INP) / 4 / 256, 256>>>(x);
    wcvt_kernel<<<dim3(G4 / 32, INP / 32), 256>>>(W);
    xw_tc_kernel<<<dim3(16, 256), 256, GEMM_SMEM_BYTES>>>(bias);
    lstm_rec_tc_kernel<<<NCTA, 256, REC4_SMEM_BYTES>>>(U, out, write_tail);
}

// round 11
// speedup vs baseline: 1.0433x; 1.0433x over previous
#include <cuda_runtime.h>
#include <cuda_bf16.h>
#include <math.h>
#include <stdint.h>

#define T_STEPS 1024
#define BATCH   32
#define INP     512
#define HID     512
#define G4      2048   // 4*HID
#define MTOT    (T_STEPS * BATCH)   // 32768

// ---------------- scratch ----------------
__device__ float g_xw[(size_t)T_STEPS * G4 * BATCH]; // [t][col][b]  (256 MB)
__device__ signed char g_xq[(size_t)MTOT * 1024];    // x 2-limb int8 [m][c*128+limb*64+ko]
__device__ signed char g_wq[(size_t)G4 * 1024];      // W^T 2-limb int8 [n][...]
__device__ signed char g_hq[2][32 * 1024];           // h 2-limb int8 ping-pong
__device__ unsigned int g_bar;                       // grid barrier counter
__device__ unsigned int g_umax_bits;                 // max|U|
__device__ unsigned int g_xmax_bits;                 // max|x|
__device__ unsigned int g_wmax_bits;                 // max|W|

// ================= helpers =================
__device__ __forceinline__ uint32_t smem_to_u32(const void* p) {
    uint32_t a;
    asm("{ .reg .u64 t; cvta.to.shared.u64 t, %1; cvt.u32.u64 %0, t; }"
        : "=r"(a) : "l"(p));
    return a;
}
#define SMEM_SWIZZLE_128B(off) ((off) ^ (((off) >> 3) & 0x70))

__device__ __forceinline__ void cp_async16(uint32_t smem_addr, const void* gptr) {
    asm volatile("cp.async.cg.shared.global [%0], [%1], 16;"
                 :: "r"(smem_addr), "l"(gptr) : "memory");
}
__device__ __forceinline__ void cp_async_commit() {
    asm volatile("cp.async.commit_group;" ::: "memory");
}
template <int N>
__device__ __forceinline__ void cp_async_wait() {
    asm volatile("cp.async.wait_group %0;" :: "n"(N) : "memory");
}

__device__ __forceinline__ void ldmatrix_x4(uint32_t* r, uint32_t addr) {
    asm volatile("ldmatrix.sync.aligned.m8n8.x4.shared.b16 {%0,%1,%2,%3}, [%4];"
                 : "=r"(r[0]), "=r"(r[1]), "=r"(r[2]), "=r"(r[3]) : "r"(addr));
}
__device__ __forceinline__ void mma_s8(int* c, const uint32_t* a, const uint32_t* b) {
    asm volatile(
        "mma.sync.aligned.m16n8k32.row.col.s32.s8.s8.s32 "
        "{%0,%1,%2,%3}, {%4,%5,%6,%7}, {%8,%9}, {%0,%1,%2,%3};"
        : "+r"(c[0]), "+r"(c[1]), "+r"(c[2]), "+r"(c[3])
        : "r"(a[0]), "r"(a[1]), "r"(a[2]), "r"(a[3]), "r"(b[0]), "r"(b[1]));
}
__device__ __forceinline__ float sigmoidf_(float v) {
    return 1.f / (1.f + __expf(-v));
}

// ---------------- init ----------------
__global__ void lstm_init_kernel() {
    int idx = blockIdx.x * blockDim.x + threadIdx.x;
    int n = 2 * 32 * 1024 / 4;
    for (int i = idx; i < n; i += gridDim.x * blockDim.x)
        ((int*)g_hq)[i] = 0;
    if (idx == 0) { g_bar = 0u; g_umax_bits = 0u; g_xmax_bits = 0u; g_wmax_bits = 0u; }
}

// ---------------- generic max|v| reduction ----------------
__global__ __launch_bounds__(256) void absmax_kernel(
    const float* __restrict__ p, int n, unsigned int* outp)
{
    __shared__ float red[256];
    float m = 0.f;
    for (int i = blockIdx.x * 256 + threadIdx.x; i < n; i += gridDim.x * 256)
        m = fmaxf(m, fabsf(p[i]));
    red[threadIdx.x] = m;
    __syncthreads();
    for (int s = 128; s > 0; s >>= 1) {
        if (threadIdx.x < s) red[threadIdx.x] = fmaxf(red[threadIdx.x], red[threadIdx.x + s]);
        __syncthreads();
    }
    if (threadIdx.x == 0)
        atomicMax(outp, __float_as_uint(red[0]));
}

// ---------------- quantize x -> 2-limb int8 ----------------
__global__ __launch_bounds__(256) void xq_kernel(const float* __restrict__ x) {
    size_t i = ((size_t)blockIdx.x * 256 + threadIdx.x) * 4;  // element index, k%4==0
    const float s = 127.f / fmaxf(__uint_as_float(g_xmax_bits), 1e-30f);
    float4 v = *(const float4*)(x + i);
    float vv[4] = {v.x, v.y, v.z, v.w};
    signed char q1[4], q2[4];
    #pragma unroll
    for (int j = 0; j < 4; j++) {
        float aq = vv[j] * s;
        int a1 = __float2int_rn(aq);
        a1 = max(-127, min(127, a1));
        int a2 = __float2int_rn((aq - (float)a1) * 254.f);
        q1[j] = (signed char)a1; q2[j] = (signed char)a2;
    }
    size_t m = i >> 9;
    int k = (int)(i & 511);
    int c = k >> 6, ko = k & 63;
    signed char* dst = g_xq + m * 1024 + c * 128 + ko;
    *(uchar4*)(dst)      = *(uchar4*)q1;
    *(uchar4*)(dst + 64) = *(uchar4*)q2;
}

// ---------------- quantize + transpose W -> [n] 2-limb int8 ----------------
__global__ __launch_bounds__(256) void wq_kernel(const float* __restrict__ W) {
    __shared__ float tile[32][33];
    const float s = 127.f / fmaxf(__uint_as_float(g_wmax_bits), 1e-30f);
    int n0 = blockIdx.x * 32, k0 = blockIdx.y * 32;
    int tx = threadIdx.x & 31, ty = threadIdx.x >> 5;   // 32 x 8
    #pragma unroll
    for (int r = 0; r < 4; r++)
        tile[ty + 8 * r][tx] = W[(size_t)(k0 + ty + 8 * r) * G4 + n0 + tx];
    __syncthreads();
    #pragma unroll
    for (int r = 0; r < 4; r++) {
        float v = tile[tx][ty + 8 * r];
        float aq = v * s;
        int p1 = __float2int_rn(aq);
        p1 = max(-127, min(127, p1));
        int p2 = __float2int_rn((aq - (float)p1) * 254.f);
        int n = n0 + ty + 8 * r;
        int k = k0 + tx;
        signed char* dst = g_wq + (size_t)n * 1024 + (k >> 6) * 128 + (k & 63);
        dst[0]  = (signed char)p1;
        dst[64] = (signed char)p2;
    }
}

// ---------------- phase 1: int8 2-limb mma GEMM ----------------
// CTA 256 thr / 8 warps. Tile M=128 x N=128, K = 8 chunks of 64, double-buffered.
// Chunk row = 128B = limb1(64B)||limb2(64B), SW128.
// s32 accumulation across all K is exact (|C| <= 1.7e7 << 2^31); fold once.
// smem: [0..512) bias; [1024..) 2 x (A 16KB + B 16KB); epilogue cs[128][129] f32.
#define GEMM_SMEM_BYTES (1024 + 128 * 129 * 4)

__global__ __launch_bounds__(256, 1) void xw_tc8_kernel(const float* __restrict__ bias)
{
    extern __shared__ char smem[];
    const uint32_t sb = smem_to_u32(smem);
    const int tid  = threadIdx.x;
    const int wid  = tid >> 5;
    const int lane = tid & 31;
    const int n0 = blockIdx.x * 128;
    const int m0 = blockIdx.y * 128;
    float* bias_sm = (float*)smem;

    if (tid < 128) bias_sm[tid] = bias[n0 + tid];

    const float s_X = fmaxf(__uint_as_float(g_xmax_bits), 1e-30f);
    const float s_W = fmaxf(__uint_as_float(g_wmax_bits), 1e-30f);
    const float sc1 = s_X * s_W / 16129.f;
    const float sc2 = sc1 / 254.f;

    // warp tile: M 64 x N 32
    const int wm = (wid & 1) * 64;
    const int wn = (wid >> 1) * 32;

    const uint32_t aRow = (uint32_t)(lane & 15);
    const uint32_t aCol = (uint32_t)(((lane >> 4) & 1) * 16);
    const uint32_t bRow = (uint32_t)(((lane >> 4) & 1) * 8 + (lane & 7));
    const uint32_t bCol = (uint32_t)(((lane >> 3) & 1) * 16);

    uint32_t aOff[4], bOff[2];
    #pragma unroll
    for (int mt = 0; mt < 4; mt++)
        aOff[mt] = (uint32_t)(wm + 16 * mt + aRow) * 128 + aCol;
    #pragma unroll
    for (int ip = 0; ip < 2; ip++)
        bOff[ip] = (uint32_t)(wn + 16 * ip + bRow) * 128 + bCol;

    int C1[4][4][4], C2[4][4][4];
    #pragma unroll
    for (int i = 0; i < 4; i++)
        #pragma unroll
        for (int j = 0; j < 4; j++)
            #pragma unroll
            for (int q = 0; q < 4; q++) { C1[i][j][q] = 0; C2[i][j][q] = 0; }

    const int lrow0 = tid >> 3;
    const int lc16  = tid & 7;

    auto issue_chunk = [&](int ch, int buf) {
        const uint32_t bbase = 1024u + (uint32_t)buf * 32768u;
        #pragma unroll
        for (int it = 0; it < 4; it++) {
            int row = lrow0 + it * 32;
            uint32_t sw = SMEM_SWIZZLE_128B((uint32_t)(row * 128 + lc16 * 16));
            cp_async16(sb + bbase + sw,
                       g_xq + (size_t)(m0 + row) * 1024 + ch * 128 + lc16 * 16);
            cp_async16(sb + bbase + 16384 + sw,
                       g_wq + (size_t)(n0 + row) * 1024 + ch * 128 + lc16 * 16);
        }
        cp_async_commit();
    };

    issue_chunk(0, 0);

    for (int ch = 0; ch < 8; ch++) {
        const int buf = ch & 1;
        if (ch < 7) issue_chunk(ch + 1, buf ^ 1);
        if (ch < 7) cp_async_wait<1>(); else cp_async_wait<0>();
        __syncthreads();

        const uint32_t bbA = sb + 1024u + (uint32_t)buf * 32768u;
        const uint32_t bbB = bbA + 16384u;
        #pragma unroll
        for (int kt = 0; kt < 2; kt++) {
            uint32_t aq1[4][4], aq2[4][4], bp1[2][4], bp2[2][4];
            #pragma unroll
            for (int mt = 0; mt < 4; mt++) {
                ldmatrix_x4(aq1[mt], bbA + SMEM_SWIZZLE_128B(aOff[mt] + kt * 32));
                ldmatrix_x4(aq2[mt], bbA + SMEM_SWIZZLE_128B(aOff[mt] + 64 + kt * 32));
            }
            #pragma unroll
            for (int ip = 0; ip < 2; ip++) {
                ldmatrix_x4(bp1[ip], bbB + SMEM_SWIZZLE_128B(bOff[ip] + kt * 32));
                ldmatrix_x4(bp2[ip], bbB + SMEM_SWIZZLE_128B(bOff[ip] + 64 + kt * 32));
            }
            #pragma unroll
            for (int mt = 0; mt < 4; mt++) {
                #pragma unroll
                for (int nt = 0; nt < 4; nt++) {
                    uint32_t* b1 = &bp1[nt >> 1][(nt & 1) * 2];
                    uint32_t* b2 = &bp2[nt >> 1][(nt & 1) * 2];
                    mma_s8(C1[mt][nt], aq1[mt], b1);
                    mma_s8(C2[mt][nt], aq1[mt], b2);
                    mma_s8(C2[mt][nt], aq2[mt], b1);
                }
            }
        }
        __syncthreads();
    }

    // ---- epilogue: fold limbs, stage in smem, coalesced writes ----
    float* cs = (float*)(smem + 1024);   // [128][129]
    const int crow = lane >> 2;
    const int ccol = (lane & 3) * 2;
    #pragma unroll
    for (int mt = 0; mt < 4; mt++) {
        #pragma unroll
        for (int nt = 0; nt < 4; nt++) {
            int r0 = wm + 16 * mt + crow;
            int cc = wn + 8 * nt + ccol;
            cs[r0 * 129 + cc]           = (float)C1[mt][nt][0] * sc1 + (float)C2[mt][nt][0] * sc2;
            cs[r0 * 129 + cc + 1]       = (float)C1[mt][nt][1] * sc1 + (float)C2[mt][nt][1] * sc2;
            cs[(r0 + 8) * 129 + cc]     = (float)C1[mt][nt][2] * sc1 + (float)C2[mt][nt][2] * sc2;
            cs[(r0 + 8) * 129 + cc + 1] = (float)C1[mt][nt][3] * sc1 + (float)C2[mt][nt][3] * sc2;
        }
    }
    __syncthreads();

    const int t0 = blockIdx.y * 4;
    for (int i = 0; i < 64; i++) {
        int ro = wid * 64 + i;
        int tl = ro >> 7, n = ro & 127;
        float v = cs[(tl * 32 + lane) * 129 + n] + bias_sm[n];
        g_xw[((size_t)(t0 + tl) * G4 + n0 + n) * BATCH + lane] = v;
    }
}

// ---------------- phase 2: int8 recurrence (R9 config, best known) -------------
// 128 CTAs x 256 threads. CTA = (unit-group ug = bid>>1, batch-half bh = bid&1):
// owns 8 hidden units (32 gate cols, gate-major n = g*8+u) x 16 batches.
// Warp w owns K-chunk w (64 k, both limbs); issues AND consumes its own cp.asyncs.
#define R_H   0
#define R_U   16384
#define R_XW  49152
#define R_P   54272
#define REC4_SMEM_BYTES 74752
#define NCTA  128

__global__ __launch_bounds__(256, 1) void lstm_rec_tc_kernel(
    const float* __restrict__ U, float* __restrict__ out, int write_tail)
{
    extern __shared__ char smem[];
    const uint32_t sb = smem_to_u32(smem);
    const int tid  = threadIdx.x;
    const int wid  = tid >> 5;
    const int lane = tid & 31;
    const int u0   = (blockIdx.x >> 1) * 8;      // unit group
    const int b0   = (blockIdx.x & 1) * 16;      // batch half

    const float s_U = fmaxf(__uint_as_float(g_umax_bits), 1e-30f);
    const float uinv = 127.f / s_U;
    const float sc1 = s_U / 16129.f;
    const float sc2 = sc1 / 254.f;

    // ---- quantize U slice -> smem int8 2-limb, chunked+swizzled ----
    for (int i = tid; i < 32 * HID; i += 256) {
        int k = i >> 5, n = i & 31;
        int gcol = u0 + (n & 7) + 512 * (n >> 3);
        float v = U[(size_t)k * G4 + gcol];
        float aq = v * uinv;
        int p1 = __float2int_rn(aq);
        p1 = max(-127, min(127, p1));
        int p2 = __float2int_rn((aq - (float)p1) * 254.f);
        int c = k >> 6, ko = k & 63;
        uint32_t base = (uint32_t)(R_U + c * 4096);
        *(signed char*)(smem + base + SMEM_SWIZZLE_128B((uint32_t)(n * 128 + ko))) =
            (signed char)p1;
        *(signed char*)(smem + base + SMEM_SWIZZLE_128B((uint32_t)(n * 128 + 64 + ko))) =
            (signed char)p2;
    }

    // ldmatrix lane address parts
    const uint32_t aRow = (uint32_t)(lane & 15);
    const uint32_t aCol = (uint32_t)(((lane >> 4) & 1) * 16);
    const uint32_t bRow = (uint32_t)(((lane >> 4) & 1) * 8 + (lane & 7));
    const uint32_t bCol = (uint32_t)(((lane >> 3) & 1) * 16);
    const uint32_t aBase = aRow * 128 + aCol;    // one m-tile (16 batches)
    const uint32_t bBase = bRow * 128 + bCol;    // n-tiles 0-1; +2048 for 2-3

    // activation mapping: thread (tid<128) owns (b = b0 + (tid>>3), u = tid&7)
    const int rb = tid >> 3;
    const int ua = tid & 7;
    float c_state = 0.f;

    float* p_sm = (float*)(smem + R_P);

    // xw prefetch: threads 0..127, 1 cp.async16 each; ALL threads commit
    auto issue_xw = [&](int t, int valid) {
        if (valid && tid < 128) {
            int n = tid >> 2, seg = tid & 3;
            int gcol = u0 + (n & 7) + 512 * (n >> 3);
            cp_async16(sb + R_XW + (uint32_t)((t & 1) * 2560 + n * 80 + seg * 16),
                       g_xw + ((size_t)t * G4 + gcol) * BATCH + b0 + seg * 4);
        }
        cp_async_commit();
    };
    // h chunk load: warp w loads chunk w, 4 cp/lane (16 rows x 8 segs)
    auto issue_h_chunk = [&](int R, int cc) {
        const signed char* hq = g_hq[R];
        #pragma unroll
        for (int j = 0; j < 4; j++) {
            int idx = lane + 32 * j;
            int b = idx >> 3, seg = idx & 7;
            uint32_t sw = SMEM_SWIZZLE_128B((uint32_t)(b * 128 + seg * 16));
            cp_async16(sb + R_H + cc * 2048 + sw,
                       hq + (b0 + b) * 1024 + cc * 128 + seg * 16);
        }
        cp_async_commit();
    };

    __syncthreads();            // U slice ready
    issue_xw(0, 1);

    for (int t = 0; t < T_STEPS; t++) {
        const int R = t & 1;

        issue_h_chunk(R, wid);              // group: h(t) chunk w
        issue_xw(t + 1, t + 1 < T_STEPS);   // group: xw(t+1) (maybe empty)
        cp_async_wait<1>();                 // drain everything except xw(t+1)

        int C1[4][4], C2[4][4];
        #pragma unroll
        for (int nt = 0; nt < 4; nt++)
            #pragma unroll
            for (int q = 0; q < 4; q++) { C1[nt][q] = 0; C2[nt][q] = 0; }

        const uint32_t hbse = sb + R_H + wid * 2048;
        const uint32_t ubse = sb + R_U + wid * 4096;
        #pragma unroll
        for (int kt = 0; kt < 2; kt++) {
            uint32_t aq1[4], aq2[4], bp1a[4], bp2a[4], bp1b[4], bp2b[4];
            ldmatrix_x4(aq1, hbse + SMEM_SWIZZLE_128B(aBase + kt * 32));
            ldmatrix_x4(aq2, hbse + SMEM_SWIZZLE_128B(aBase + 64 + kt * 32));
            ldmatrix_x4(bp1a, ubse + SMEM_SWIZZLE_128B(bBase + kt * 32));
            ldmatrix_x4(bp2a, ubse + SMEM_SWIZZLE_128B(bBase + 64 + kt * 32));
            ldmatrix_x4(bp1b, ubse + 2048 + SMEM_SWIZZLE_128B(bBase + kt * 32));
            ldmatrix_x4(bp2b, ubse + 2048 + SMEM_SWIZZLE_128B(bBase + 64 + kt * 32));
            #pragma unroll
            for (int nt = 0; nt < 4; nt++) {
                uint32_t* b1 = (nt < 2) ? &bp1a[(nt & 1) * 2] : &bp1b[(nt & 1) * 2];
                uint32_t* b2 = (nt < 2) ? &bp2a[(nt & 1) * 2] : &bp2b[(nt & 1) * 2];
                mma_s8(C1[nt], aq1, b1);
                mma_s8(C2[nt], aq1, b2);
                mma_s8(C2[nt], aq2, b1);
            }
        }

        // combine limbs -> float partials [w][16 m][40]
        {
            const int m  = lane >> 2;
            const int nn = 2 * (lane & 3);
            #pragma unroll
            for (int nt = 0; nt < 4; nt++) {
                int col = nt * 8 + nn;
                float e0 = (float)C1[nt][0] * sc1 + (float)C2[nt][0] * sc2;
                float e1 = (float)C1[nt][1] * sc1 + (float)C2[nt][1] * sc2;
                float e2 = (float)C1[nt][2] * sc1 + (float)C2[nt][2] * sc2;
                float e3 = (float)C1[nt][3] * sc1 + (float)C2[nt][3] * sc2;
                *(float2*)&p_sm[(wid * 16 + m) * 40 + col]     = make_float2(e0, e1);
                *(float2*)&p_sm[(wid * 16 + m + 8) * 40 + col] = make_float2(e2, e3);
            }
        }
        __syncthreads();   // partials + xw(t) visible to all threads

        // reduce + activations (tid < 128): thread owns (rb, ua)
        if (tid < 128) {
            const float* xw_sm = (const float*)(smem + R_XW + (t & 1) * 2560);
            float s[4];
            #pragma unroll
            for (int g = 0; g < 4; g++) {
                int n = g * 8 + ua;
                float v = xw_sm[n * 20 + rb];
                #pragma unroll
                for (int w = 0; w < 8; w++)
                    v += p_sm[(w * 16 + rb) * 40 + n];
                s[g] = v;
            }
            float ig = sigmoidf_(s[0]);
            float fg = sigmoidf_(s[1]);
            float gg = tanhf(s[2]);
            float og = sigmoidf_(s[3]);
            float cnew = fg * c_state + ig * gg;
            float hnew = og * tanhf(cnew);
            c_state = cnew;

            const int b = b0 + rb;
            out[((size_t)t * BATCH + b) * HID + u0 + ua] = hnew;

            // quantize h -> 2 int8 limbs
            float aq = hnew * 127.f;
            int q1 = __float2int_rn(aq);
            q1 = max(-127, min(127, q1));
            int q2 = __float2int_rn((aq - (float)q1) * 254.f);
            int uu = u0 + ua;
            int cc2 = uu >> 6, ko = uu & 63;
            signed char* dst = g_hq[R ^ 1] + b * 1024 + cc2 * 128 + ko;
            dst[0]  = (signed char)q1;
            dst[64] = (signed char)q2;

            if (write_tail && t == T_STEPS - 1) {
                out[(size_t)T_STEPS * BATCH * HID + (size_t)b * HID + u0 + ua] = hnew;
                out[(size_t)T_STEPS * BATCH * HID + BATCH * HID
                    + (size_t)b * HID + u0 + ua] = cnew;
            }
        }
        __syncthreads();   // h stores complete before the release below

        // grid barrier (single counter, tid0 poll)
        if (t + 1 < T_STEPS) {
            if (tid == 0) {
                unsigned int target = (unsigned int)NCTA * (unsigned int)(t + 1);
                asm volatile("red.release.gpu.add.u32 [%0], %1;"
                             :: "l"(&g_bar), "r"(1u) : "memory");
                unsigned int v;
                do {
                    asm volatile("ld.acquire.gpu.u32 %0, [%1];"
                                 : "=r"(v) : "l"(&g_bar) : "memory");
                } while (v < target);
            }
            __syncthreads();
        }
    }
}

// ---------------- launch ----------------
extern "C" void kernel_launch(void* const* d_in, const int* in_sizes, int n_in,
                              void* d_out, int out_size)
{
    const float* x    = (const float*)d_in[0]; // (T,B,I)
    const float* W    = (const float*)d_in[1]; // (I,4H)
    const float* U    = (const float*)d_in[2]; // (H,4H)
    const float* bias = (const float*)d_in[3]; // (4H,)
    float* out = (float*)d_out;

    const long long need_tail = (long long)T_STEPS * BATCH * HID + 2LL * BATCH * HID;
    int write_tail = ((long long)out_size >= need_tail) ? 1 : 0;

    static int configured = 0;
    if (!configured) {
        cudaFuncSetAttribute(xw_tc8_kernel,
                             cudaFuncAttributeMaxDynamicSharedMemorySize,
                             GEMM_SMEM_BYTES);
        cudaFuncSetAttribute(lstm_rec_tc_kernel,
                             cudaFuncAttributeMaxDynamicSharedMemorySize,
                             REC4_SMEM_BYTES);
        configured = 1;
    }

    unsigned int* d_umax;
    unsigned int* d_xmax;
    unsigned int* d_wmax;
    cudaGetSymbolAddress((void**)&d_umax, g_umax_bits);
    cudaGetSymbolAddress((void**)&d_xmax, g_xmax_bits);
    cudaGetSymbolAddress((void**)&d_wmax, g_wmax_bits);

    lstm_init_kernel<<<64, 256>>>();
    absmax_kernel<<<256, 256>>>(U, HID * G4, d_umax);
    absmax_kernel<<<256, 256>>>(W, INP * G4, d_wmax);
    absmax_kernel<<<256, 256>>>(x, MTOT * INP, d_xmax);
    xq_kernel<<<(MTOT * INP) / 4 / 256, 256>>>(x);
    wq_kernel<<<dim3(G4 / 32, INP / 32), 256>>>(W);
    xw_tc8_kernel<<<dim3(16, 256), 256, GEMM_SMEM_BYTES>>>(bias);
    lstm_rec_tc_kernel<<<NCTA, 256, REC4_SMEM_BYTES>>>(U, out, write_tail);
}

// round 12
// speedup vs baseline: 1.0833x; 1.0383x over previous
#include <cuda_runtime.h>
#include <cuda_bf16.h>
#include <math.h>
#include <stdint.h>

#define T_STEPS 1024
#define BATCH   32
#define INP     512
#define HID     512
#define G4      2048   // 4*HID
#define MTOT    (T_STEPS * BATCH)   // 32768

// ---------------- scratch ----------------
__device__ float g_xw[(size_t)T_STEPS * G4 * BATCH]; // [t][col][b]  (256 MB)
__device__ signed char g_xq[(size_t)MTOT * 1024];    // x 2-limb int8 [m][c*128+limb*64+ko]
__device__ signed char g_wq[(size_t)G4 * 1024];      // W^T 2-limb int8 [n][...]
__device__ signed char g_hq[2][32 * 1024];           // h 2-limb int8 ping-pong
__device__ unsigned int g_bar;                       // grid barrier counter
__device__ unsigned int g_umax_bits;                 // max|U|
__device__ unsigned int g_xmax_bits;                 // max|x|
__device__ unsigned int g_wmax_bits;                 // max|W|

// ================= helpers =================
__device__ __forceinline__ uint32_t smem_to_u32(const void* p) {
    uint32_t a;
    asm("{ .reg .u64 t; cvta.to.shared.u64 t, %1; cvt.u32.u64 %0, t; }"
        : "=r"(a) : "l"(p));
    return a;
}
#define SMEM_SWIZZLE_128B(off) ((off) ^ (((off) >> 3) & 0x70))

__device__ __forceinline__ void cp_async16(uint32_t smem_addr, const void* gptr) {
    asm volatile("cp.async.cg.shared.global [%0], [%1], 16;"
                 :: "r"(smem_addr), "l"(gptr) : "memory");
}
__device__ __forceinline__ void cp_async_commit() {
    asm volatile("cp.async.commit_group;" ::: "memory");
}
template <int N>
__device__ __forceinline__ void cp_async_wait() {
    asm volatile("cp.async.wait_group %0;" :: "n"(N) : "memory");
}

__device__ __forceinline__ void ldmatrix_x4(uint32_t* r, uint32_t addr) {
    asm volatile("ldmatrix.sync.aligned.m8n8.x4.shared.b16 {%0,%1,%2,%3}, [%4];"
                 : "=r"(r[0]), "=r"(r[1]), "=r"(r[2]), "=r"(r[3]) : "r"(addr));
}
__device__ __forceinline__ void mma_s8(int* c, const uint32_t* a, const uint32_t* b) {
    asm volatile(
        "mma.sync.aligned.m16n8k32.row.col.s32.s8.s8.s32 "
        "{%0,%1,%2,%3}, {%4,%5,%6,%7}, {%8,%9}, {%0,%1,%2,%3};"
        : "+r"(c[0]), "+r"(c[1]), "+r"(c[2]), "+r"(c[3])
        : "r"(a[0]), "r"(a[1]), "r"(a[2]), "r"(a[3]), "r"(b[0]), "r"(b[1]));
}
__device__ __forceinline__ float sigmoidf_(float v) {
    return 1.f / (1.f + __expf(-v));
}

// ---------------- init ----------------
__global__ void lstm_init_kernel() {
    int idx = blockIdx.x * blockDim.x + threadIdx.x;
    int n = 2 * 32 * 1024 / 4;
    for (int i = idx; i < n; i += gridDim.x * blockDim.x)
        ((int*)g_hq)[i] = 0;
    if (idx == 0) { g_bar = 0u; g_umax_bits = 0u; g_xmax_bits = 0u; g_wmax_bits = 0u; }
}

// ---------------- fast max|v| reduction: float4 + 4 accumulators ---------------
__global__ __launch_bounds__(256) void absmax4_kernel(
    const float4* __restrict__ p, int n4, unsigned int* outp)
{
    float m0 = 0.f, m1 = 0.f, m2 = 0.f, m3 = 0.f;
    const int stride = gridDim.x * 256;
    for (int i = blockIdx.x * 256 + threadIdx.x; i < n4; i += stride) {
        float4 v = p[i];
        m0 = fmaxf(m0, fabsf(v.x));
        m1 = fmaxf(m1, fabsf(v.y));
        m2 = fmaxf(m2, fabsf(v.z));
        m3 = fmaxf(m3, fabsf(v.w));
    }
    float m = fmaxf(fmaxf(m0, m1), fmaxf(m2, m3));
    #pragma unroll
    for (int s = 16; s > 0; s >>= 1)
        m = fmaxf(m, __shfl_xor_sync(0xFFFFFFFFu, m, s));
    __shared__ float red[8];
    if ((threadIdx.x & 31) == 0) red[threadIdx.x >> 5] = m;
    __syncthreads();
    if (threadIdx.x == 0) {
        float r = red[0];
        #pragma unroll
        for (int w = 1; w < 8; w++) r = fmaxf(r, red[w]);
        atomicMax(outp, __float_as_uint(r));
    }
}

// ---------------- quantize x -> 2-limb int8 ----------------
__global__ __launch_bounds__(256) void xq_kernel(const float* __restrict__ x) {
    size_t i = ((size_t)blockIdx.x * 256 + threadIdx.x) * 4;  // element index, k%4==0
    const float s = 127.f / fmaxf(__uint_as_float(g_xmax_bits), 1e-30f);
    float4 v = *(const float4*)(x + i);
    float vv[4] = {v.x, v.y, v.z, v.w};
    signed char q1[4], q2[4];
    #pragma unroll
    for (int j = 0; j < 4; j++) {
        float aq = vv[j] * s;
        int a1 = __float2int_rn(aq);
        a1 = max(-127, min(127, a1));
        int a2 = __float2int_rn((aq - (float)a1) * 254.f);
        q1[j] = (signed char)a1; q2[j] = (signed char)a2;
    }
    size_t m = i >> 9;
    int k = (int)(i & 511);
    int c = k >> 6, ko = k & 63;
    signed char* dst = g_xq + m * 1024 + c * 128 + ko;
    *(uchar4*)(dst)      = *(uchar4*)q1;
    *(uchar4*)(dst + 64) = *(uchar4*)q2;
}

// ---------------- quantize + transpose W -> [n] 2-limb int8 ----------------
__global__ __launch_bounds__(256) void wq_kernel(const float* __restrict__ W) {
    __shared__ float tile[32][33];
    const float s = 127.f / fmaxf(__uint_as_float(g_wmax_bits), 1e-30f);
    int n0 = blockIdx.x * 32, k0 = blockIdx.y * 32;
    int tx = threadIdx.x & 31, ty = threadIdx.x >> 5;   // 32 x 8
    #pragma unroll
    for (int r = 0; r < 4; r++)
        tile[ty + 8 * r][tx] = W[(size_t)(k0 + ty + 8 * r) * G4 + n0 + tx];
    __syncthreads();
    #pragma unroll
    for (int r = 0; r < 4; r++) {
        float v = tile[tx][ty + 8 * r];
        float aq = v * s;
        int p1 = __float2int_rn(aq);
        p1 = max(-127, min(127, p1));
        int p2 = __float2int_rn((aq - (float)p1) * 254.f);
        int n = n0 + ty + 8 * r;
        int k = k0 + tx;
        signed char* dst = g_wq + (size_t)n * 1024 + (k >> 6) * 128 + (k & 63);
        dst[0]  = (signed char)p1;
        dst[64] = (signed char)p2;
    }
}

// ---------------- phase 1: int8 2-limb mma GEMM (unchanged from R11) -----------
#define GEMM_SMEM_BYTES (1024 + 128 * 129 * 4)

__global__ __launch_bounds__(256, 1) void xw_tc8_kernel(const float* __restrict__ bias)
{
    extern __shared__ char smem[];
    const uint32_t sb = smem_to_u32(smem);
    const int tid  = threadIdx.x;
    const int wid  = tid >> 5;
    const int lane = tid & 31;
    const int n0 = blockIdx.x * 128;
    const int m0 = blockIdx.y * 128;
    float* bias_sm = (float*)smem;

    if (tid < 128) bias_sm[tid] = bias[n0 + tid];

    const float s_X = fmaxf(__uint_as_float(g_xmax_bits), 1e-30f);
    const float s_W = fmaxf(__uint_as_float(g_wmax_bits), 1e-30f);
    const float sc1 = s_X * s_W / 16129.f;
    const float sc2 = sc1 / 254.f;

    const int wm = (wid & 1) * 64;
    const int wn = (wid >> 1) * 32;

    const uint32_t aRow = (uint32_t)(lane & 15);
    const uint32_t aCol = (uint32_t)(((lane >> 4) & 1) * 16);
    const uint32_t bRow = (uint32_t)(((lane >> 4) & 1) * 8 + (lane & 7));
    const uint32_t bCol = (uint32_t)(((lane >> 3) & 1) * 16);

    uint32_t aOff[4], bOff[2];
    #pragma unroll
    for (int mt = 0; mt < 4; mt++)
        aOff[mt] = (uint32_t)(wm + 16 * mt + aRow) * 128 + aCol;
    #pragma unroll
    for (int ip = 0; ip < 2; ip++)
        bOff[ip] = (uint32_t)(wn + 16 * ip + bRow) * 128 + bCol;

    int C1[4][4][4], C2[4][4][4];
    #pragma unroll
    for (int i = 0; i < 4; i++)
        #pragma unroll
        for (int j = 0; j < 4; j++)
            #pragma unroll
            for (int q = 0; q < 4; q++) { C1[i][j][q] = 0; C2[i][j][q] = 0; }

    const int lrow0 = tid >> 3;
    const int lc16  = tid & 7;

    auto issue_chunk = [&](int ch, int buf) {
        const uint32_t bbase = 1024u + (uint32_t)buf * 32768u;
        #pragma unroll
        for (int it = 0; it < 4; it++) {
            int row = lrow0 + it * 32;
            uint32_t sw = SMEM_SWIZZLE_128B((uint32_t)(row * 128 + lc16 * 16));
            cp_async16(sb + bbase + sw,
                       g_xq + (size_t)(m0 + row) * 1024 + ch * 128 + lc16 * 16);
            cp_async16(sb + bbase + 16384 + sw,
                       g_wq + (size_t)(n0 + row) * 1024 + ch * 128 + lc16 * 16);
        }
        cp_async_commit();
    };

    issue_chunk(0, 0);

    for (int ch = 0; ch < 8; ch++) {
        const int buf = ch & 1;
        if (ch < 7) issue_chunk(ch + 1, buf ^ 1);
        if (ch < 7) cp_async_wait<1>(); else cp_async_wait<0>();
        __syncthreads();

        const uint32_t bbA = sb + 1024u + (uint32_t)buf * 32768u;
        const uint32_t bbB = bbA + 16384u;
        #pragma unroll
        for (int kt = 0; kt < 2; kt++) {
            uint32_t aq1[4][4], aq2[4][4], bp1[2][4], bp2[2][4];
            #pragma unroll
            for (int mt = 0; mt < 4; mt++) {
                ldmatrix_x4(aq1[mt], bbA + SMEM_SWIZZLE_128B(aOff[mt] + kt * 32));
                ldmatrix_x4(aq2[mt], bbA + SMEM_SWIZZLE_128B(aOff[mt] + 64 + kt * 32));
            }
            #pragma unroll
            for (int ip = 0; ip < 2; ip++) {
                ldmatrix_x4(bp1[ip], bbB + SMEM_SWIZZLE_128B(bOff[ip] + kt * 32));
                ldmatrix_x4(bp2[ip], bbB + SMEM_SWIZZLE_128B(bOff[ip] + 64 + kt * 32));
            }
            #pragma unroll
            for (int mt = 0; mt < 4; mt++) {
                #pragma unroll
                for (int nt = 0; nt < 4; nt++) {
                    uint32_t* b1 = &bp1[nt >> 1][(nt & 1) * 2];
                    uint32_t* b2 = &bp2[nt >> 1][(nt & 1) * 2];
                    mma_s8(C1[mt][nt], aq1[mt], b1);
                    mma_s8(C2[mt][nt], aq1[mt], b2);
                    mma_s8(C2[mt][nt], aq2[mt], b1);
                }
            }
        }
        __syncthreads();
    }

    float* cs = (float*)(smem + 1024);   // [128][129]
    const int crow = lane >> 2;
    const int ccol = (lane & 3) * 2;
    #pragma unroll
    for (int mt = 0; mt < 4; mt++) {
        #pragma unroll
        for (int nt = 0; nt < 4; nt++) {
            int r0 = wm + 16 * mt + crow;
            int cc = wn + 8 * nt + ccol;
            cs[r0 * 129 + cc]           = (float)C1[mt][nt][0] * sc1 + (float)C2[mt][nt][0] * sc2;
            cs[r0 * 129 + cc + 1]       = (float)C1[mt][nt][1] * sc1 + (float)C2[mt][nt][1] * sc2;
            cs[(r0 + 8) * 129 + cc]     = (float)C1[mt][nt][2] * sc1 + (float)C2[mt][nt][2] * sc2;
            cs[(r0 + 8) * 129 + cc + 1] = (float)C1[mt][nt][3] * sc1 + (float)C2[mt][nt][3] * sc2;
        }
    }
    __syncthreads();

    const int t0 = blockIdx.y * 4;
    for (int i = 0; i < 64; i++) {
        int ro = wid * 64 + i;
        int tl = ro >> 7, n = ro & 127;
        float v = cs[(tl * 32 + lane) * 129 + n] + bias_sm[n];
        g_xw[((size_t)(t0 + tl) * G4 + n0 + n) * BATCH + lane] = v;
    }
}

// ---------------- phase 2: int8 recurrence (unchanged from R11/R9) -------------
#define R_H   0
#define R_U   16384
#define R_XW  49152
#define R_P   54272
#define REC4_SMEM_BYTES 74752
#define NCTA  128

__global__ __launch_bounds__(256, 1) void lstm_rec_tc_kernel(
    const float* __restrict__ U, float* __restrict__ out, int write_tail)
{
    extern __shared__ char smem[];
    const uint32_t sb = smem_to_u32(smem);
    const int tid  = threadIdx.x;
    const int wid  = tid >> 5;
    const int lane = tid & 31;
    const int u0   = (blockIdx.x >> 1) * 8;      // unit group
    const int b0   = (blockIdx.x & 1) * 16;      // batch half

    const float s_U = fmaxf(__uint_as_float(g_umax_bits), 1e-30f);
    const float uinv = 127.f / s_U;
    const float sc1 = s_U / 16129.f;
    const float sc2 = sc1 / 254.f;

    // ---- quantize U slice -> smem int8 2-limb, chunked+swizzled ----
    for (int i = tid; i < 32 * HID; i += 256) {
        int k = i >> 5, n = i & 31;
        int gcol = u0 + (n & 7) + 512 * (n >> 3);
        float v = U[(size_t)k * G4 + gcol];
        float aq = v * uinv;
        int p1 = __float2int_rn(aq);
        p1 = max(-127, min(127, p1));
        int p2 = __float2int_rn((aq - (float)p1) * 254.f);
        int c = k >> 6, ko = k & 63;
        uint32_t base = (uint32_t)(R_U + c * 4096);
        *(signed char*)(smem + base + SMEM_SWIZZLE_128B((uint32_t)(n * 128 + ko))) =
            (signed char)p1;
        *(signed char*)(smem + base + SMEM_SWIZZLE_128B((uint32_t)(n * 128 + 64 + ko))) =
            (signed char)p2;
    }

    const uint32_t aRow = (uint32_t)(lane & 15);
    const uint32_t aCol = (uint32_t)(((lane >> 4) & 1) * 16);
    const uint32_t bRow = (uint32_t)(((lane >> 4) & 1) * 8 + (lane & 7));
    const uint32_t bCol = (uint32_t)(((lane >> 3) & 1) * 16);
    const uint32_t aBase = aRow * 128 + aCol;    // one m-tile (16 batches)
    const uint32_t bBase = bRow * 128 + bCol;    // n-tiles 0-1; +2048 for 2-3

    const int rb = tid >> 3;
    const int ua = tid & 7;
    float c_state = 0.f;

    float* p_sm = (float*)(smem + R_P);

    auto issue_xw = [&](int t, int valid) {
        if (valid && tid < 128) {
            int n = tid >> 2, seg = tid & 3;
            int gcol = u0 + (n & 7) + 512 * (n >> 3);
            cp_async16(sb + R_XW + (uint32_t)((t & 1) * 2560 + n * 80 + seg * 16),
                       g_xw + ((size_t)t * G4 + gcol) * BATCH + b0 + seg * 4);
        }
        cp_async_commit();
    };
    auto issue_h_chunk = [&](int R, int cc) {
        const signed char* hq = g_hq[R];
        #pragma unroll
        for (int j = 0; j < 4; j++) {
            int idx = lane + 32 * j;
            int b = idx >> 3, seg = idx & 7;
            uint32_t sw = SMEM_SWIZZLE_128B((uint32_t)(b * 128 + seg * 16));
            cp_async16(sb + R_H + cc * 2048 + sw,
                       hq + (b0 + b) * 1024 + cc * 128 + seg * 16);
        }
        cp_async_commit();
    };

    __syncthreads();            // U slice ready
    issue_xw(0, 1);

    for (int t = 0; t < T_STEPS; t++) {
        const int R = t & 1;

        issue_h_chunk(R, wid);              // group: h(t) chunk w
        issue_xw(t + 1, t + 1 < T_STEPS);   // group: xw(t+1) (maybe empty)
        cp_async_wait<1>();                 // drain everything except xw(t+1)

        int C1[4][4], C2[4][4];
        #pragma unroll
        for (int nt = 0; nt < 4; nt++)
            #pragma unroll
            for (int q = 0; q < 4; q++) { C1[nt][q] = 0; C2[nt][q] = 0; }

        const uint32_t hbse = sb + R_H + wid * 2048;
        const uint32_t ubse = sb + R_U + wid * 4096;
        #pragma unroll
        for (int kt = 0; kt < 2; kt++) {
            uint32_t aq1[4], aq2[4], bp1a[4], bp2a[4], bp1b[4], bp2b[4];
            ldmatrix_x4(aq1, hbse + SMEM_SWIZZLE_128B(aBase + kt * 32));
            ldmatrix_x4(aq2, hbse + SMEM_SWIZZLE_128B(aBase + 64 + kt * 32));
            ldmatrix_x4(bp1a, ubse + SMEM_SWIZZLE_128B(bBase + kt * 32));
            ldmatrix_x4(bp2a, ubse + SMEM_SWIZZLE_128B(bBase + 64 + kt * 32));
            ldmatrix_x4(bp1b, ubse + 2048 + SMEM_SWIZZLE_128B(bBase + kt * 32));
            ldmatrix_x4(bp2b, ubse + 2048 + SMEM_SWIZZLE_128B(bBase + 64 + kt * 32));
            #pragma unroll
            for (int nt = 0; nt < 4; nt++) {
                uint32_t* b1 = (nt < 2) ? &bp1a[(nt & 1) * 2] : &bp1b[(nt & 1) * 2];
                uint32_t* b2 = (nt < 2) ? &bp2a[(nt & 1) * 2] : &bp2b[(nt & 1) * 2];
                mma_s8(C1[nt], aq1, b1);
                mma_s8(C2[nt], aq1, b2);
                mma_s8(C2[nt], aq2, b1);
            }
        }

        {
            const int m  = lane >> 2;
            const int nn = 2 * (lane & 3);
            #pragma unroll
            for (int nt = 0; nt < 4; nt++) {
                int col = nt * 8 + nn;
                float e0 = (float)C1[nt][0] * sc1 + (float)C2[nt][0] * sc2;
                float e1 = (float)C1[nt][1] * sc1 + (float)C2[nt][1] * sc2;
                float e2 = (float)C1[nt][2] * sc1 + (float)C2[nt][2] * sc2;
                float e3 = (float)C1[nt][3] * sc1 + (float)C2[nt][3] * sc2;
                *(float2*)&p_sm[(wid * 16 + m) * 40 + col]     = make_float2(e0, e1);
                *(float2*)&p_sm[(wid * 16 + m + 8) * 40 + col] = make_float2(e2, e3);
            }
        }
        __syncthreads();   // partials + xw(t) visible to all threads

        if (tid < 128) {
            const float* xw_sm = (const float*)(smem + R_XW + (t & 1) * 2560);
            float s[4];
            #pragma unroll
            for (int g = 0; g < 4; g++) {
                int n = g * 8 + ua;
                float v = xw_sm[n * 20 + rb];
                #pragma unroll
                for (int w = 0; w < 8; w++)
                    v += p_sm[(w * 16 + rb) * 40 + n];
                s[g] = v;
            }
            float ig = sigmoidf_(s[0]);
            float fg = sigmoidf_(s[1]);
            float gg = tanhf(s[2]);
            float og = sigmoidf_(s[3]);
            float cnew = fg * c_state + ig * gg;
            float hnew = og * tanhf(cnew);
            c_state = cnew;

            const int b = b0 + rb;
            out[((size_t)t * BATCH + b) * HID + u0 + ua] = hnew;

            float aq = hnew * 127.f;
            int q1 = __float2int_rn(aq);
            q1 = max(-127, min(127, q1));
            int q2 = __float2int_rn((aq - (float)q1) * 254.f);
            int uu = u0 + ua;
            int cc2 = uu >> 6, ko = uu & 63;
            signed char* dst = g_hq[R ^ 1] + b * 1024 + cc2 * 128 + ko;
            dst[0]  = (signed char)q1;
            dst[64] = (signed char)q2;

            if (write_tail && t == T_STEPS - 1) {
                out[(size_t)T_STEPS * BATCH * HID + (size_t)b * HID + u0 + ua] = hnew;
                out[(size_t)T_STEPS * BATCH * HID + BATCH * HID
                    + (size_t)b * HID + u0 + ua] = cnew;
            }
        }
        __syncthreads();   // h stores complete before the release below

        if (t + 1 < T_STEPS) {
            if (tid == 0) {
                unsigned int target = (unsigned int)NCTA * (unsigned int)(t + 1);
                asm volatile("red.release.gpu.add.u32 [%0], %1;"
                             :: "l"(&g_bar), "r"(1u) : "memory");
                unsigned int v;
                do {
                    asm volatile("ld.acquire.gpu.u32 %0, [%1];"
                                 : "=r"(v) : "l"(&g_bar) : "memory");
                } while (v < target);
            }
            __syncthreads();
        }
    }
}

// ---------------- launch ----------------
extern "C" void kernel_launch(void* const* d_in, const int* in_sizes, int n_in,
                              void* d_out, int out_size)
{
    const float* x    = (const float*)d_in[0]; // (T,B,I)
    const float* W    = (const float*)d_in[1]; // (I,4H)
    const float* U    = (const float*)d_in[2]; // (H,4H)
    const float* bias = (const float*)d_in[3]; // (4H,)
    float* out = (float*)d_out;

    const long long need_tail = (long long)T_STEPS * BATCH * HID + 2LL * BATCH * HID;
    int write_tail = ((long long)out_size >= need_tail) ? 1 : 0;

    static int configured = 0;
    if (!configured) {
        cudaFuncSetAttribute(xw_tc8_kernel,
                             cudaFuncAttributeMaxDynamicSharedMemorySize,
                             GEMM_SMEM_BYTES);
        cudaFuncSetAttribute(lstm_rec_tc_kernel,
                             cudaFuncAttributeMaxDynamicSharedMemorySize,
                             REC4_SMEM_BYTES);
        configured = 1;
    }

    unsigned int* d_umax;
    unsigned int* d_xmax;
    unsigned int* d_wmax;
    cudaGetSymbolAddress((void**)&d_umax, g_umax_bits);
    cudaGetSymbolAddress((void**)&d_xmax, g_xmax_bits);
    cudaGetSymbolAddress((void**)&d_wmax, g_wmax_bits);

    lstm_init_kernel<<<64, 256>>>();
    absmax4_kernel<<<512, 256>>>((const float4*)U, HID * G4 / 4, d_umax);
    absmax4_kernel<<<512, 256>>>((const float4*)W, INP * G4 / 4, d_wmax);
    absmax4_kernel<<<1024, 256>>>((const float4*)x, MTOT * INP / 4, d_xmax);
    xq_kernel<<<(MTOT * INP) / 4 / 256, 256>>>(x);
    wq_kernel<<<dim3(G4 / 32, INP / 32), 256>>>(W);
    xw_tc8_kernel<<<dim3(16, 256), 256, GEMM_SMEM_BYTES>>>(bias);
    lstm_rec_tc_kernel<<<NCTA, 256, REC4_SMEM_BYTES>>>(U, out, write_tail);
}

// round 13
// speedup vs baseline: 1.2344x; 1.1395x over previous
#include <cuda_runtime.h>
#include <cuda_bf16.h>
#include <math.h>
#include <stdint.h>

#define T_STEPS 1024
#define BATCH   32
#define INP     512
#define HID     512
#define G4      2048   // 4*HID
#define MTOT    (T_STEPS * BATCH)   // 32768

// ---------------- scratch ----------------
__device__ signed char g_xq[(size_t)MTOT * 1024];    // x 2-limb int8 [m][c*128+limb*64+ko]
__device__ signed char g_hq[2][32 * 1024];           // h 2-limb int8 ping-pong
__device__ unsigned int g_bar;                       // grid barrier counter
__device__ unsigned int g_umax_bits;                 // max|U|
__device__ unsigned int g_xmax_bits;                 // max|x|
__device__ unsigned int g_wmax_bits;                 // max|W|

// ================= helpers =================
__device__ __forceinline__ uint32_t smem_to_u32(const void* p) {
    uint32_t a;
    asm("{ .reg .u64 t; cvta.to.shared.u64 t, %1; cvt.u32.u64 %0, t; }"
        : "=r"(a) : "l"(p));
    return a;
}
#define SMEM_SWIZZLE_128B(off) ((off) ^ (((off) >> 3) & 0x70))

__device__ __forceinline__ void cp_async16(uint32_t smem_addr, const void* gptr) {
    asm volatile("cp.async.cg.shared.global [%0], [%1], 16;"
                 :: "r"(smem_addr), "l"(gptr) : "memory");
}
__device__ __forceinline__ void cp_async_commit() {
    asm volatile("cp.async.commit_group;" ::: "memory");
}
template <int N>
__device__ __forceinline__ void cp_async_wait() {
    asm volatile("cp.async.wait_group %0;" :: "n"(N) : "memory");
}

__device__ __forceinline__ void ldmatrix_x4(uint32_t* r, uint32_t addr) {
    asm volatile("ldmatrix.sync.aligned.m8n8.x4.shared.b16 {%0,%1,%2,%3}, [%4];"
                 : "=r"(r[0]), "=r"(r[1]), "=r"(r[2]), "=r"(r[3]) : "r"(addr));
}
__device__ __forceinline__ void mma_s8(int* c, const uint32_t* a, const uint32_t* b) {
    asm volatile(
        "mma.sync.aligned.m16n8k32.row.col.s32.s8.s8.s32 "
        "{%0,%1,%2,%3}, {%4,%5,%6,%7}, {%8,%9}, {%0,%1,%2,%3};"
        : "+r"(c[0]), "+r"(c[1]), "+r"(c[2]), "+r"(c[3])
        : "r"(a[0]), "r"(a[1]), "r"(a[2]), "r"(a[3]), "r"(b[0]), "r"(b[1]));
}
__device__ __forceinline__ float sigmoidf_(float v) {
    return 1.f / (1.f + __expf(-v));
}

// ---------------- init ----------------
__global__ void lstm_init_kernel() {
    int idx = blockIdx.x * blockDim.x + threadIdx.x;
    int n = 2 * 32 * 1024 / 4;
    for (int i = idx; i < n; i += gridDim.x * blockDim.x)
        ((int*)g_hq)[i] = 0;
    if (idx == 0) { g_bar = 0u; g_umax_bits = 0u; g_xmax_bits = 0u; g_wmax_bits = 0u; }
}

// ---------------- fast max|v| reduction ----------------
__global__ __launch_bounds__(256) void absmax4_kernel(
    const float4* __restrict__ p, int n4, unsigned int* outp)
{
    float m0 = 0.f, m1 = 0.f, m2 = 0.f, m3 = 0.f;
    const int stride = gridDim.x * 256;
    for (int i = blockIdx.x * 256 + threadIdx.x; i < n4; i += stride) {
        float4 v = p[i];
        m0 = fmaxf(m0, fabsf(v.x));
        m1 = fmaxf(m1, fabsf(v.y));
        m2 = fmaxf(m2, fabsf(v.z));
        m3 = fmaxf(m3, fabsf(v.w));
    }
    float m = fmaxf(fmaxf(m0, m1), fmaxf(m2, m3));
    #pragma unroll
    for (int s = 16; s > 0; s >>= 1)
        m = fmaxf(m, __shfl_xor_sync(0xFFFFFFFFu, m, s));
    __shared__ float red[8];
    if ((threadIdx.x & 31) == 0) red[threadIdx.x >> 5] = m;
    __syncthreads();
    if (threadIdx.x == 0) {
        float r = red[0];
        #pragma unroll
        for (int w = 1; w < 8; w++) r = fmaxf(r, red[w]);
        atomicMax(outp, __float_as_uint(r));
    }
}

// ---------------- quantize x -> 2-limb int8 ----------------
__global__ __launch_bounds__(256) void xq_kernel(const float* __restrict__ x) {
    size_t i = ((size_t)blockIdx.x * 256 + threadIdx.x) * 4;  // element index, k%4==0
    const float s = 127.f / fmaxf(__uint_as_float(g_xmax_bits), 1e-30f);
    float4 v = *(const float4*)(x + i);
    float vv[4] = {v.x, v.y, v.z, v.w};
    signed char q1[4], q2[4];
    #pragma unroll
    for (int j = 0; j < 4; j++) {
        float aq = vv[j] * s;
        int a1 = __float2int_rn(aq);
        a1 = max(-127, min(127, a1));
        int a2 = __float2int_rn((aq - (float)a1) * 254.f);
        q1[j] = (signed char)a1; q2[j] = (signed char)a2;
    }
    size_t m = i >> 9;
    int k = (int)(i & 511);
    int c = k >> 6, ko = k & 63;
    signed char* dst = g_xq + m * 1024 + c * 128 + ko;
    *(uchar4*)(dst)      = *(uchar4*)q1;
    *(uchar4*)(dst + 64) = *(uchar4*)q2;
}

// ---------------- fused persistent kernel: recurrence + input GEMM -------------
// 128 CTAs x 256 threads. CTA = (unit-group ug = bid>>1, batch-half bh = bid&1):
// owns 8 hidden units (32 gate cols, gate-major n = g*8+u) x 16 batches.
// Per step t:
//   1. load h(t) chunk w + x(t+1) chunk w (warp-owned cp.async groups)
//   2. h mma -> partials -> reduce + activations -> store h(t+1)
//   3. release grid barrier (consumers can proceed)
//   4. IN THE BARRIER BUBBLE: xw(t+1) = x(t+1) @ W_slice + bias  (24 mma/warp)
//   5. poll barrier
// smem bytes:
//   [0      .. 16384)  h: 8 chunks of [16 b][128B = limb1|limb2], SW128
//   [16384  .. 32768)  x: 8 chunks of [16 b][128B]
//   [32768  .. 65536)  U: 8 chunks of [32 n][128B]
//   [65536  .. 98304)  W: 8 chunks of [32 n][128B]
//   [98304  ..103424)  xw double buffer, 2 x [32 n][20 f] (stride 80B)
//   [103424 ..103552)  bias slice [32 n]
//   [103552 ..124032)  partials [8 w][16 m][40 f]
#define R_H    0
#define R_X    16384
#define R_U    32768
#define R_W    65536
#define R_XW   98304
#define R_BIAS 103424
#define R_P    103552
#define REC5_SMEM_BYTES 124032
#define NCTA  128

__global__ __launch_bounds__(256, 1) void lstm_fused_kernel(
    const float* __restrict__ U, const float* __restrict__ W,
    const float* __restrict__ bias, float* __restrict__ out, int write_tail)
{
    extern __shared__ char smem[];
    const uint32_t sb = smem_to_u32(smem);
    const int tid  = threadIdx.x;
    const int wid  = tid >> 5;
    const int lane = tid & 31;
    const int u0   = (blockIdx.x >> 1) * 8;      // unit group
    const int b0   = (blockIdx.x & 1) * 16;      // batch half

    const float s_U = fmaxf(__uint_as_float(g_umax_bits), 1e-30f);
    const float s_X = fmaxf(__uint_as_float(g_xmax_bits), 1e-30f);
    const float s_W = fmaxf(__uint_as_float(g_wmax_bits), 1e-30f);
    const float uinv = 127.f / s_U;
    const float winv = 127.f / s_W;
    const float sc1  = s_U / 16129.f;            // h@U combine scales
    const float sc2  = sc1 / 254.f;
    const float sx1  = s_X * s_W / 16129.f;      // x@W combine scales
    const float sx2  = sx1 / 254.f;

    // ---- quantize U and W slices -> smem int8 2-limb, chunked+swizzled ----
    for (int i = tid; i < 32 * HID; i += 256) {
        int k = i >> 5, n = i & 31;
        int gcol = u0 + (n & 7) + 512 * (n >> 3);
        int c = k >> 6, ko = k & 63;
        uint32_t sw1 = SMEM_SWIZZLE_128B((uint32_t)(n * 128 + ko));
        uint32_t sw2 = SMEM_SWIZZLE_128B((uint32_t)(n * 128 + 64 + ko));
        {
            float v = U[(size_t)k * G4 + gcol];
            float aq = v * uinv;
            int p1 = __float2int_rn(aq);
            p1 = max(-127, min(127, p1));
            int p2 = __float2int_rn((aq - (float)p1) * 254.f);
            uint32_t base = (uint32_t)(R_U + c * 4096);
            *(signed char*)(smem + base + sw1) = (signed char)p1;
            *(signed char*)(smem + base + sw2) = (signed char)p2;
        }
        {
            float v = W[(size_t)k * G4 + gcol];
            float aq = v * winv;
            int p1 = __float2int_rn(aq);
            p1 = max(-127, min(127, p1));
            int p2 = __float2int_rn((aq - (float)p1) * 254.f);
            uint32_t base = (uint32_t)(R_W + c * 4096);
            *(signed char*)(smem + base + sw1) = (signed char)p1;
            *(signed char*)(smem + base + sw2) = (signed char)p2;
        }
    }
    if (tid < 32) {
        int gcol = u0 + (tid & 7) + 512 * (tid >> 3);
        ((float*)(smem + R_BIAS))[tid] = bias[gcol];
    }

    // ldmatrix lane address parts
    const uint32_t aRow = (uint32_t)(lane & 15);
    const uint32_t aCol = (uint32_t)(((lane >> 4) & 1) * 16);
    const uint32_t bRow = (uint32_t)(((lane >> 4) & 1) * 8 + (lane & 7));
    const uint32_t bCol = (uint32_t)(((lane >> 3) & 1) * 16);
    const uint32_t aBase = aRow * 128 + aCol;    // one m-tile (16 rows)
    const uint32_t bBase = bRow * 128 + bCol;    // n-tiles 0-1; +2048 for 2-3

    // activation mapping: thread (tid<128) owns (b = b0 + (tid>>3), u = tid&7)
    const int rb = tid >> 3;
    const int ua = tid & 7;
    float c_state = 0.f;

    float* p_sm = (float*)(smem + R_P);
    const float* bias_sm = (const float*)(smem + R_BIAS);

    // x chunk load for step t: warp w loads chunk w (always commits a group)
    auto issue_x_chunk = [&](int t, int valid) {
        if (valid) {
            const signed char* xq = g_xq + (size_t)t * 32 * 1024;
            #pragma unroll
            for (int j = 0; j < 4; j++) {
                int idx = lane + 32 * j;
                int b = idx >> 3, seg = idx & 7;
                uint32_t sw = SMEM_SWIZZLE_128B((uint32_t)(b * 128 + seg * 16));
                cp_async16(sb + R_X + wid * 2048 + sw,
                           xq + (b0 + b) * 1024 + wid * 128 + seg * 16);
            }
        }
        cp_async_commit();
    };
    // h chunk load: warp w loads chunk w
    auto issue_h_chunk = [&](int R) {
        const signed char* hq = g_hq[R];
        #pragma unroll
        for (int j = 0; j < 4; j++) {
            int idx = lane + 32 * j;
            int b = idx >> 3, seg = idx & 7;
            uint32_t sw = SMEM_SWIZZLE_128B((uint32_t)(b * 128 + seg * 16));
            cp_async16(sb + R_H + wid * 2048 + sw,
                       hq + (b0 + b) * 1024 + wid * 128 + seg * 16);
        }
        cp_async_commit();
    };

    // xw compute for step t into slot t&1: A = x buffer chunk w, B = W chunk w
    auto compute_xw = [&](int t) {
        int X1[4][4], X2[4][4];
        #pragma unroll
        for (int nt = 0; nt < 4; nt++)
            #pragma unroll
            for (int q = 0; q < 4; q++) { X1[nt][q] = 0; X2[nt][q] = 0; }
        const uint32_t xbse = sb + R_X + wid * 2048;
        const uint32_t wbse = sb + R_W + wid * 4096;
        #pragma unroll
        for (int kt = 0; kt < 2; kt++) {
            uint32_t aq1[4], aq2[4], bp1a[4], bp2a[4], bp1b[4], bp2b[4];
            ldmatrix_x4(aq1, xbse + SMEM_SWIZZLE_128B(aBase + kt * 32));
            ldmatrix_x4(aq2, xbse + SMEM_SWIZZLE_128B(aBase + 64 + kt * 32));
            ldmatrix_x4(bp1a, wbse + SMEM_SWIZZLE_128B(bBase + kt * 32));
            ldmatrix_x4(bp2a, wbse + SMEM_SWIZZLE_128B(bBase + 64 + kt * 32));
            ldmatrix_x4(bp1b, wbse + 2048 + SMEM_SWIZZLE_128B(bBase + kt * 32));
            ldmatrix_x4(bp2b, wbse + 2048 + SMEM_SWIZZLE_128B(bBase + 64 + kt * 32));
            #pragma unroll
            for (int nt = 0; nt < 4; nt++) {
                uint32_t* b1 = (nt < 2) ? &bp1a[(nt & 1) * 2] : &bp1b[(nt & 1) * 2];
                uint32_t* b2 = (nt < 2) ? &bp2a[(nt & 1) * 2] : &bp2b[(nt & 1) * 2];
                mma_s8(X1[nt], aq1, b1);
                mma_s8(X2[nt], aq1, b2);
                mma_s8(X2[nt], aq2, b1);
            }
        }
        {
            const int m  = lane >> 2;
            const int nn = 2 * (lane & 3);
            #pragma unroll
            for (int nt = 0; nt < 4; nt++) {
                int col = nt * 8 + nn;
                float e0 = (float)X1[nt][0] * sx1 + (float)X2[nt][0] * sx2;
                float e1 = (float)X1[nt][1] * sx1 + (float)X2[nt][1] * sx2;
                float e2 = (float)X1[nt][2] * sx1 + (float)X2[nt][2] * sx2;
                float e3 = (float)X1[nt][3] * sx1 + (float)X2[nt][3] * sx2;
                *(float2*)&p_sm[(wid * 16 + m) * 40 + col]     = make_float2(e0, e1);
                *(float2*)&p_sm[(wid * 16 + m + 8) * 40 + col] = make_float2(e2, e3);
            }
        }
        __syncthreads();   // xw partials visible
        // fold + bias -> xw_sm slot t&1 (conflict-free reads: n = lane)
        if (tid < 128) {
            int n = tid & 31;
            int bq = (tid >> 5) * 4;
            float* dst = (float*)(smem + R_XW + (uint32_t)((t & 1) * 2560));
            #pragma unroll
            for (int bi = 0; bi < 4; bi++) {
                int b = bq + bi;
                float v = bias_sm[n];
                #pragma unroll
                for (int w = 0; w < 8; w++)
                    v += p_sm[(w * 16 + b) * 40 + n];
                dst[n * 20 + b] = v;
            }
        }
    };

    __syncthreads();            // U/W slices + bias ready

    // ---- prologue: xw(0) into slot 0 ----
    issue_x_chunk(0, 1);
    cp_async_wait<0>();
    compute_xw(0);
    __syncthreads();            // xw(0) ready (and p_sm free)

    for (int t = 0; t < T_STEPS; t++) {
        const int R = t & 1;

        issue_h_chunk(R);                     // group: h(t) chunk w
        issue_x_chunk(t + 1, t + 1 < T_STEPS);// group: x(t+1) (maybe empty)
        cp_async_wait<1>();                   // h ready (x pending)

        // ---- h @ U ----
        int C1[4][4], C2[4][4];
        #pragma unroll
        for (int nt = 0; nt < 4; nt++)
            #pragma unroll
            for (int q = 0; q < 4; q++) { C1[nt][q] = 0; C2[nt][q] = 0; }

        const uint32_t hbse = sb + R_H + wid * 2048;
        const uint32_t ubse = sb + R_U + wid * 4096;
        #pragma unroll
        for (int kt = 0; kt < 2; kt++) {
            uint32_t aq1[4], aq2[4], bp1a[4], bp2a[4], bp1b[4], bp2b[4];
            ldmatrix_x4(aq1, hbse + SMEM_SWIZZLE_128B(aBase + kt * 32));
            ldmatrix_x4(aq2, hbse + SMEM_SWIZZLE_128B(aBase + 64 + kt * 32));
            ldmatrix_x4(bp1a, ubse + SMEM_SWIZZLE_128B(bBase + kt * 32));
            ldmatrix_x4(bp2a, ubse + SMEM_SWIZZLE_128B(bBase + 64 + kt * 32));
            ldmatrix_x4(bp1b, ubse + 2048 + SMEM_SWIZZLE_128B(bBase + kt * 32));
            ldmatrix_x4(bp2b, ubse + 2048 + SMEM_SWIZZLE_128B(bBase + 64 + kt * 32));
            #pragma unroll
            for (int nt = 0; nt < 4; nt++) {
                uint32_t* b1 = (nt < 2) ? &bp1a[(nt & 1) * 2] : &bp1b[(nt & 1) * 2];
                uint32_t* b2 = (nt < 2) ? &bp2a[(nt & 1) * 2] : &bp2b[(nt & 1) * 2];
                mma_s8(C1[nt], aq1, b1);
                mma_s8(C2[nt], aq1, b2);
                mma_s8(C2[nt], aq2, b1);
            }
        }
        {
            const int m  = lane >> 2;
            const int nn = 2 * (lane & 3);
            #pragma unroll
            for (int nt = 0; nt < 4; nt++) {
                int col = nt * 8 + nn;
                float e0 = (float)C1[nt][0] * sc1 + (float)C2[nt][0] * sc2;
                float e1 = (float)C1[nt][1] * sc1 + (float)C2[nt][1] * sc2;
                float e2 = (float)C1[nt][2] * sc1 + (float)C2[nt][2] * sc2;
                float e3 = (float)C1[nt][3] * sc1 + (float)C2[nt][3] * sc2;
                *(float2*)&p_sm[(wid * 16 + m) * 40 + col]     = make_float2(e0, e1);
                *(float2*)&p_sm[(wid * 16 + m + 8) * 40 + col] = make_float2(e2, e3);
            }
        }
        __syncthreads();   // h partials + xw(t) visible

        // ---- reduce + activations (tid < 128): thread owns (rb, ua) ----
        if (tid < 128) {
            const float* xw_sm = (const float*)(smem + R_XW + (uint32_t)((t & 1) * 2560));
            float s[4];
            #pragma unroll
            for (int g = 0; g < 4; g++) {
                int n = g * 8 + ua;
                float v = xw_sm[n * 20 + rb];
                #pragma unroll
                for (int w = 0; w < 8; w++)
                    v += p_sm[(w * 16 + rb) * 40 + n];
                s[g] = v;
            }
            float ig = sigmoidf_(s[0]);
            float fg = sigmoidf_(s[1]);
            float gg = tanhf(s[2]);
            float og = sigmoidf_(s[3]);
            float cnew = fg * c_state + ig * gg;
            float hnew = og * tanhf(cnew);
            c_state = cnew;

            const int b = b0 + rb;
            out[((size_t)t * BATCH + b) * HID + u0 + ua] = hnew;

            float aq = hnew * 127.f;
            int q1 = __float2int_rn(aq);
            q1 = max(-127, min(127, q1));
            int q2 = __float2int_rn((aq - (float)q1) * 254.f);
            int uu = u0 + ua;
            int cc2 = uu >> 6, ko = uu & 63;
            signed char* dst = g_hq[R ^ 1] + b * 1024 + cc2 * 128 + ko;
            dst[0]  = (signed char)q1;
            dst[64] = (signed char)q2;

            if (write_tail && t == T_STEPS - 1) {
                out[(size_t)T_STEPS * BATCH * HID + (size_t)b * HID + u0 + ua] = hnew;
                out[(size_t)T_STEPS * BATCH * HID + BATCH * HID
                    + (size_t)b * HID + u0 + ua] = cnew;
            }
        }
        __syncthreads();   // h stores + p_sm/xw reads complete

        if (t + 1 < T_STEPS) {
            // release EARLY: consumers can start while we compute xw(t+1)
            if (tid == 0) {
                asm volatile("red.release.gpu.add.u32 [%0], %1;"
                             :: "l"(&g_bar), "r"(1u) : "memory");
            }
            // ---- x(t+1) @ W in the barrier bubble ----
            cp_async_wait<0>();   // x(t+1) ready
            compute_xw(t + 1);
            // ---- poll barrier ----
            if (tid == 0) {
                unsigned int target = (unsigned int)NCTA * (unsigned int)(t + 1);
                unsigned int v;
                do {
                    asm volatile("ld.acquire.gpu.u32 %0, [%1];"
                                 : "=r"(v) : "l"(&g_bar) : "memory");
                } while (v < target);
            }
            __syncthreads();      // orders fold reads before next-step p_sm writes
        }
    }
}

// ---------------- launch ----------------
extern "C" void kernel_launch(void* const* d_in, const int* in_sizes, int n_in,
                              void* d_out, int out_size)
{
    const float* x    = (const float*)d_in[0]; // (T,B,I)
    const float* W    = (const float*)d_in[1]; // (I,4H)
    const float* U    = (const float*)d_in[2]; // (H,4H)
    const float* bias = (const float*)d_in[3]; // (4H,)
    float* out = (float*)d_out;

    const long long need_tail = (long long)T_STEPS * BATCH * HID + 2LL * BATCH * HID;
    int write_tail = ((long long)out_size >= need_tail) ? 1 : 0;

    static int configured = 0;
    if (!configured) {
        cudaFuncSetAttribute(lstm_fused_kernel,
                             cudaFuncAttributeMaxDynamicSharedMemorySize,
                             REC5_SMEM_BYTES);
        configured = 1;
    }

    unsigned int* d_umax;
    unsigned int* d_xmax;
    unsigned int* d_wmax;
    cudaGetSymbolAddress((void**)&d_umax, g_umax_bits);
    cudaGetSymbolAddress((void**)&d_xmax, g_xmax_bits);
    cudaGetSymbolAddress((void**)&d_wmax, g_wmax_bits);

    lstm_init_kernel<<<64, 256>>>();
    absmax4_kernel<<<512, 256>>>((const float4*)U, HID * G4 / 4, d_umax);
    absmax4_kernel<<<512, 256>>>((const float4*)W, INP * G4 / 4, d_wmax);
    absmax4_kernel<<<1024, 256>>>((const float4*)x, MTOT * INP / 4, d_xmax);
    xq_kernel<<<(MTOT * INP) / 4 / 256, 256>>>(x);
    lstm_fused_kernel<<<NCTA, 256, REC5_SMEM_BYTES>>>(U, W, bias, out, write_tail);
}